// round 2
// baseline (speedup 1.0000x reference)
#include <cuda_runtime.h>

#define Bsz 16
#define Tsz 2048
#define WN  512
#define Dd  300
#define DP  308   // padded row stride in smem (mod 32 = 20 -> <=2-way bank conflicts)
#define TT  64    // t-rows per CTA
#define WC  64    // w-chunk
#define PP  68    // probs row stride
#define NT  256

// scratch for proj = attn @ W_h^T  (bias dropped: constant per t-row, softmax-invariant)
__device__ float g_proj[2u * Bsz * WN * Dd];

// ---------------------------------------------------------------------------
// proj kernel: proj[h][b][w][d] = sum_k attn[b][w][k] * W_h[d][k]
// 64x64 tile, K staged 32 at a time, 4x4 micro-tiles.
// ---------------------------------------------------------------------------
__global__ __launch_bounds__(NT, 1) void proj_kernel(
    const float* __restrict__ attn,
    const float* __restrict__ W2,
    const float* __restrict__ W3)
{
    __shared__ float sA[64 * 36];
    __shared__ float sB[64 * 36];
    const int h = blockIdx.z & 1, b = blockIdx.z >> 1;
    const float* Wm = h ? W3 : W2;
    const int w0 = blockIdx.x * 64, d0 = blockIdx.y * 64;
    const int tid = threadIdx.x, txS = tid & 15, tyS = tid >> 4;
    const float* A = attn + (size_t)b * WN * Dd;

    float c[4][4];
#pragma unroll
    for (int i = 0; i < 4; i++)
#pragma unroll
        for (int j = 0; j < 4; j++) c[i][j] = 0.f;

    for (int k0 = 0; k0 < Dd; k0 += 32) {
        __syncthreads();
        for (int i = tid; i < 64 * 8; i += NT) {
            int r = i >> 3, c4 = i & 7, k = k0 + c4 * 4;
            float4 v = make_float4(0.f, 0.f, 0.f, 0.f);
            if (k < Dd) v = *(const float4*)(A + (size_t)(w0 + r) * Dd + k);
            *(float4*)&sA[r * 36 + c4 * 4] = v;
        }
        for (int i = tid; i < 64 * 8; i += NT) {
            int r = i >> 3, c4 = i & 7, k = k0 + c4 * 4, d = d0 + r;
            float4 v = make_float4(0.f, 0.f, 0.f, 0.f);
            if (k < Dd && d < Dd) v = *(const float4*)(Wm + (size_t)d * Dd + k);
            *(float4*)&sB[r * 36 + c4 * 4] = v;
        }
        __syncthreads();
#pragma unroll
        for (int k = 0; k < 32; k += 4) {
            float4 a4[4], b4[4];
#pragma unroll
            for (int i = 0; i < 4; i++) a4[i] = *(float4*)&sA[(tyS + 16 * i) * 36 + k];
#pragma unroll
            for (int j = 0; j < 4; j++) b4[j] = *(float4*)&sB[(txS + 16 * j) * 36 + k];
#pragma unroll
            for (int i = 0; i < 4; i++)
#pragma unroll
                for (int j = 0; j < 4; j++) {
                    c[i][j] += a4[i].x * b4[j].x;
                    c[i][j] += a4[i].y * b4[j].y;
                    c[i][j] += a4[i].z * b4[j].z;
                    c[i][j] += a4[i].w * b4[j].w;
                }
        }
    }
    float* P = g_proj + ((size_t)h * Bsz + b) * WN * Dd;
#pragma unroll
    for (int i = 0; i < 4; i++) {
        int w = w0 + tyS + 16 * i;
#pragma unroll
        for (int j = 0; j < 4; j++) {
            int d = d0 + txS + 16 * j;
            if (d < Dd) P[(size_t)w * Dd + d] = c[i][j];
        }
    }
}

// ---------------------------------------------------------------------------
// fused attend kernel (flash-style, fp32):
//   grid (T/64, B, 2 heads), 256 threads, 1 CTA/SM (171 KB smem)
//   per chunk of 64 windows: S = main_tile @ proj_chunk^T (4x4 micro),
//   online softmax (shfl over 16-lane row groups), acc += P @ attn_chunk
//   (register acc: 4 rows x 19 d-cols per thread).
// ---------------------------------------------------------------------------
__global__ __launch_bounds__(NT, 1) void attend_kernel(
    const float* __restrict__ x1,   // [B,T,D]
    const float* __restrict__ x2,   // [B,WN,D]
    float* __restrict__ out)        // [2,B,T,D]
{
    extern __shared__ float sm[];
    float* sMain  = sm;               // TT*DP
    float* sChunk = sm + TT * DP;     // WC*DP (proj, then attn)
    float* sP     = sm + 2 * TT * DP; // TT*PP
    const int t0 = blockIdx.x * TT, b = blockIdx.y, h = blockIdx.z;
    const int tid = threadIdx.x, txS = tid & 15, tyS = tid >> 4;

    const float* mainB = x1 + ((size_t)b * Tsz + t0) * Dd;
    const float* attnB = x2 + (size_t)b * WN * Dd;
    const float* projB = g_proj + ((size_t)h * Bsz + b) * WN * Dd;

    for (int i = tid; i < TT * 75; i += NT) {
        int r = i / 75, c4 = i % 75;
        *(float4*)&sMain[r * DP + c4 * 4] = *(const float4*)(mainB + (size_t)r * Dd + c4 * 4);
    }

    float acc[4][19];
    float m_i[4], l_i[4];
#pragma unroll
    for (int i = 0; i < 4; i++) {
        m_i[i] = -1e30f; l_i[i] = 0.f;
#pragma unroll
        for (int j = 0; j < 19; j++) acc[i][j] = 0.f;
    }

    for (int w0 = 0; w0 < WN; w0 += WC) {
        __syncthreads();  // previous chunk's readers of sChunk are done
        for (int i = tid; i < WC * 75; i += NT) {
            int r = i / 75, c4 = i % 75;
            *(float4*)&sChunk[r * DP + c4 * 4] =
                *(const float4*)(projB + (size_t)(w0 + r) * Dd + c4 * 4);
        }
        __syncthreads();

        // --- scores: S[4][4] in registers ---
        float s[4][4];
#pragma unroll
        for (int i = 0; i < 4; i++)
#pragma unroll
            for (int j = 0; j < 4; j++) s[i][j] = 0.f;

#pragma unroll 3
        for (int k = 0; k < Dd; k += 4) {
            float4 a4[4], b4[4];
#pragma unroll
            for (int i = 0; i < 4; i++) a4[i] = *(float4*)&sMain[(tyS + 16 * i) * DP + k];
#pragma unroll
            for (int j = 0; j < 4; j++) b4[j] = *(float4*)&sChunk[(txS + 16 * j) * DP + k];
#pragma unroll
            for (int i = 0; i < 4; i++)
#pragma unroll
                for (int j = 0; j < 4; j++) {
                    s[i][j] += a4[i].x * b4[j].x;
                    s[i][j] += a4[i].y * b4[j].y;
                    s[i][j] += a4[i].z * b4[j].z;
                    s[i][j] += a4[i].w * b4[j].w;
                }
        }

        // --- online softmax over this chunk (row groups = 16 lanes same tyS) ---
#pragma unroll
        for (int i = 0; i < 4; i++) {
            float cmax = fmaxf(fmaxf(s[i][0], s[i][1]), fmaxf(s[i][2], s[i][3]));
#pragma unroll
            for (int o = 8; o >= 1; o >>= 1)
                cmax = fmaxf(cmax, __shfl_xor_sync(0xffffffffu, cmax, o));
            float newm = fmaxf(m_i[i], cmax);
            float alpha = __expf(m_i[i] - newm);
            float csum = 0.f;
#pragma unroll
            for (int j = 0; j < 4; j++) {
                float p = __expf(s[i][j] - newm);
                s[i][j] = p; csum += p;
            }
#pragma unroll
            for (int o = 8; o >= 1; o >>= 1)
                csum += __shfl_xor_sync(0xffffffffu, csum, o);
            l_i[i] = l_i[i] * alpha + csum;
            m_i[i] = newm;
#pragma unroll
            for (int j = 0; j < 19; j++) acc[i][j] *= alpha;
#pragma unroll
            for (int j = 0; j < 4; j++)
                sP[(tyS + 16 * i) * PP + txS + 16 * j] = s[i][j];
        }
        __syncthreads();  // sP complete; sChunk (proj) no longer needed

        // --- load attn chunk into sChunk ---
        for (int i = tid; i < WC * 75; i += NT) {
            int r = i / 75, c4 = i % 75;
            *(float4*)&sChunk[r * DP + c4 * 4] =
                *(const float4*)(attnB + (size_t)(w0 + r) * Dd + c4 * 4);
        }
        __syncthreads();

        // --- acc += P @ attn_chunk ---
#pragma unroll 2
        for (int w = 0; w < WC; w++) {
            float p0 = sP[(tyS     ) * PP + w];
            float p1 = sP[(tyS + 16) * PP + w];
            float p2 = sP[(tyS + 32) * PP + w];
            float p3 = sP[(tyS + 48) * PP + w];
            const float* ar = &sChunk[w * DP + txS * 19];
#pragma unroll
            for (int j = 0; j < 19; j++) {
                float av = ar[j];
                acc[0][j] += p0 * av;
                acc[1][j] += p1 * av;
                acc[2][j] += p2 * av;
                acc[3][j] += p3 * av;
            }
        }
    }

    // --- epilogue: normalize, stage through sMain, coalesced store ---
    float inv[4];
#pragma unroll
    for (int i = 0; i < 4; i++) inv[i] = 1.0f / l_i[i];
#pragma unroll
    for (int i = 0; i < 4; i++)
#pragma unroll
        for (int j = 0; j < 19; j++)
            sMain[(tyS + 16 * i) * DP + txS * 19 + j] = acc[i][j] * inv[i];
    __syncthreads();
    float* outB = out + (((size_t)h * Bsz + b) * Tsz + t0) * Dd;
    for (int i = tid; i < TT * 75; i += NT) {
        int r = i / 75, c4 = i % 75;
        *(float4*)(outB + (size_t)r * Dd + c4 * 4) = *(float4*)&sMain[r * DP + c4 * 4];
    }
}

// ---------------------------------------------------------------------------
extern "C" void kernel_launch(void* const* d_in, const int* in_sizes, int n_in,
                              void* d_out, int out_size)
{
    const float* x1 = (const float*)d_in[0];  // input1 [16,2048,300]
    const float* x2 = (const float*)d_in[1];  // input2 [16,512,300]
    const float* W2 = (const float*)d_in[2];  // [300,300]
    // d_in[3] = b2 (unused: softmax-invariant)
    const float* W3 = (const float*)d_in[4];  // [300,300]
    // d_in[5] = b3 (unused), d_in[6] = mode (always 1)
    float* out = (float*)d_out;               // [2,16,2048,300]

    proj_kernel<<<dim3(WN / 64, (Dd + 63) / 64, Bsz * 2), NT>>>(x2, W2, W3);

    size_t smem = (size_t)(2 * TT * DP + TT * PP) * sizeof(float);  // 175104 B
    cudaFuncSetAttribute(attend_kernel,
                         cudaFuncAttributeMaxDynamicSharedMemorySize, (int)smem);
    attend_kernel<<<dim3(Tsz / TT, Bsz, 2), NT, smem>>>(x1, x2, out);
}

// round 14
// speedup vs baseline: 2.2129x; 2.2129x over previous
#include <cuda_runtime.h>
#include <cuda_fp16.h>
#include <cstdint>

#define NB 16
#define NT_ 2048
#define NW 512
#define ND 300
#define KD 320      // padded d (K and N), 320 = 20x16
#define THREADS 256

// ---------------- device scratch ----------------
__device__ __half g_main_hi[(size_t)NB*NT_*KD];
__device__ __half g_main_lo[(size_t)NB*NT_*KD];
__device__ __half g_attn_hi[(size_t)NB*NW*KD];
__device__ __half g_attn_lo[(size_t)NB*NW*KD];
__device__ __half g_attnT_hi[(size_t)NB*KD*NW];
__device__ __half g_attnT_lo[(size_t)NB*KD*NW];
__device__ __half g_W_hi[2*KD*KD];
__device__ __half g_W_lo[2*KD*KD];
__device__ __half g_proj_hi[(size_t)2*NB*NW*KD];
__device__ __half g_proj_lo[(size_t)2*NB*NW*KD];
__device__ __half g_P[(size_t)2*NB*NT_*NW];

// ---------------- PTX helpers ----------------
__device__ __forceinline__ uint32_t smem_u32(const void* p) {
    uint32_t a;
    asm("{ .reg .u64 t; cvta.to.shared.u64 t, %1; cvt.u32.u64 %0, t; }" : "=r"(a) : "l"(p));
    return a;
}
__device__ __forceinline__ void ldm_x4(uint32_t* r, uint32_t a) {
    asm volatile("ldmatrix.sync.aligned.m8n8.x4.shared.b16 {%0,%1,%2,%3}, [%4];"
        : "=r"(r[0]), "=r"(r[1]), "=r"(r[2]), "=r"(r[3]) : "r"(a));
}
__device__ __forceinline__ void mma16816(float* c, const uint32_t* a, uint32_t b0, uint32_t b1) {
    asm volatile("mma.sync.aligned.m16n8k16.row.col.f32.f16.f16.f32 "
        "{%0,%1,%2,%3}, {%4,%5,%6,%7}, {%8,%9}, {%0,%1,%2,%3};"
        : "+f"(c[0]), "+f"(c[1]), "+f"(c[2]), "+f"(c[3])
        : "r"(a[0]), "r"(a[1]), "r"(a[2]), "r"(a[3]), "r"(b0), "r"(b1));
}
__device__ __forceinline__ void cpa16(uint32_t dst, const void* src) {
    asm volatile("cp.async.cg.shared.global [%0], [%1], 16;" :: "r"(dst), "l"(src));
}
#define CP_COMMIT() asm volatile("cp.async.commit_group;")
#define CP_WAIT0()  asm volatile("cp.async.wait_group 0;")

// ---------------- prep kernels ----------------
// split one padded row (ND->KD) into fp16 hi/lo
__global__ void prep_split(const float* __restrict__ src, int which) {
    int r = blockIdx.x, c = threadIdx.x;            // 320 threads
    float v = (c < ND) ? src[(size_t)r * ND + c] : 0.f;
    __half hi = __float2half_rn(v);
    __half lo = __float2half_rn(v - __half2float(hi));
    size_t o = (size_t)r * KD + c;
    if (which == 0) { g_main_hi[o] = hi; g_main_lo[o] = lo; }
    else            { g_attn_hi[o] = hi; g_attn_lo[o] = lo; }
}
__global__ void prep_W(const float* __restrict__ W2, const float* __restrict__ W3) {
    int h = blockIdx.y, r = blockIdx.x, c = threadIdx.x;   // 320x2 blocks, 320 threads
    const float* W = h ? W3 : W2;
    float v = (r < ND && c < ND) ? W[(size_t)r * ND + c] : 0.f;
    __half hi = __float2half_rn(v);
    size_t o = ((size_t)h * KD + r) * KD + c;
    g_W_hi[o] = hi;
    g_W_lo[o] = __float2half_rn(v - __half2float(hi));
}
__global__ void prep_attnT(const float* __restrict__ attn) {
    __shared__ float t[32][33];
    int b = blockIdx.z, w0 = blockIdx.x * 32, d0 = blockIdx.y * 32;
    int tx = threadIdx.x, ty = threadIdx.y;
    for (int j = ty; j < 32; j += 8) {
        int d = d0 + tx;
        t[j][tx] = (d < ND) ? attn[((size_t)b * NW + w0 + j) * ND + d] : 0.f;
    }
    __syncthreads();
    for (int j = ty; j < 32; j += 8) {
        int d = d0 + j;
        float v = t[tx][j];
        __half hi = __float2half_rn(v);
        size_t o = ((size_t)b * KD + d) * NW + w0 + tx;
        g_attnT_hi[o] = hi;
        g_attnT_lo[o] = __float2half_rn(v - __half2float(hi));
    }
}

// ---------------- proj kernel: proj[h,b,w,:] = attn[b,w,:] @ W[h]^T ----------------
// CTA [64 w, 320 dout], grid (8, NB, 2). K=320 in 10 slices of 32, double-buffered.
__global__ __launch_bounds__(THREADS, 1) void proj_kernel() {
    extern __shared__ char sm[];
    const int w0 = blockIdx.x * 64, b = blockIdx.y, h = blockIdx.z;
    int tid = threadIdx.x, wid = tid >> 5, lane = tid & 31;
    int wr = wid >> 1, wcn = wid & 1;
    uint32_t sb = smem_u32(sm);
    const uint32_t oAh = 0, oAl = 41984;                    // 64 x 656B
    const uint32_t oB[2][2] = {{83968, 109568}, {135168, 160768}};  // 320 x 80B each

    const __half* gah = g_attn_hi + ((size_t)b * NW + w0) * KD;
    const __half* gal = g_attn_lo + ((size_t)b * NW + w0) * KD;
    const __half* gwh = g_W_hi + (size_t)h * KD * KD;
    const __half* gwl = g_W_lo + (size_t)h * KD * KD;

    for (int i = tid; i < 64 * 40; i += THREADS) {          // resident A hi/lo
        int r = i / 40, c = i % 40;
        *(uint4*)(sm + oAh + r * 656 + c * 16) = *(const uint4*)(gah + (size_t)r * KD + c * 8);
        *(uint4*)(sm + oAl + r * 656 + c * 16) = *(const uint4*)(gal + (size_t)r * KD + c * 8);
    }
    auto load_slice = [&](int buf, int ks) {
        for (int i = tid; i < 320 * 4; i += THREADS) {
            int r = i >> 2, c = i & 3;
            cpa16(sb + oB[buf][0] + r * 80 + c * 16, gwh + (size_t)r * KD + ks * 32 + c * 8);
            cpa16(sb + oB[buf][1] + r * 80 + c * 16, gwl + (size_t)r * KD + ks * 32 + c * 8);
        }
        CP_COMMIT();
    };
    load_slice(0, 0);

    float acc[20][4];
#pragma unroll
    for (int t = 0; t < 20; t++)
#pragma unroll
        for (int j = 0; j < 4; j++) acc[t][j] = 0.f;

    for (int ks = 0; ks < 10; ks++) {
        CP_WAIT0();
        __syncthreads();
        if (ks < 9) load_slice((ks + 1) & 1, ks + 1);
        int buf = ks & 1;
#pragma unroll
        for (int k16 = 0; k16 < 2; k16++) {
            uint32_t aH[4], aL[4];
            int colA = ks * 32 + k16 * 16 + ((lane >> 4) << 3);
            uint32_t ar = sb + (wr * 16 + (lane & 15)) * 656 + colA * 2;
            ldm_x4(aH, oAh + ar);
            ldm_x4(aL, oAl + ar);
#pragma unroll
            for (int tp = 0; tp < 10; tp++) {
                int n = wcn * 160 + tp * 16;
                uint32_t r = n + (lane & 7) + ((lane >> 4) << 3);
                uint32_t c = k16 * 16 + (((lane >> 3) & 1) << 3);
                uint32_t bh[4], bl[4];
                ldm_x4(bh, sb + oB[buf][0] + r * 80 + c * 2);
                ldm_x4(bl, sb + oB[buf][1] + r * 80 + c * 2);
                mma16816(acc[2 * tp],     aH, bh[0], bh[1]);
                mma16816(acc[2 * tp + 1], aH, bh[2], bh[3]);
                mma16816(acc[2 * tp],     aH, bl[0], bl[1]);
                mma16816(acc[2 * tp + 1], aH, bl[2], bl[3]);
                mma16816(acc[2 * tp],     aL, bh[0], bh[1]);
                mma16816(acc[2 * tp + 1], aL, bh[2], bh[3]);
            }
        }
    }
    // epilogue: split to hi/lo fp16
    size_t pbase = ((size_t)h * NB + b) * NW + w0 + wr * 16 + (lane >> 2);
#pragma unroll
    for (int t = 0; t < 20; t++) {
        int d = wcn * 160 + t * 8 + 2 * (lane & 3);
#pragma unroll
        for (int rr = 0; rr < 2; rr++) {
            float v0 = acc[t][rr * 2], v1 = acc[t][rr * 2 + 1];
            __half h0 = __float2half_rn(v0), h1 = __float2half_rn(v1);
            __half l0 = __float2half_rn(v0 - __half2float(h0));
            __half l1 = __float2half_rn(v1 - __half2float(h1));
            size_t o = (pbase + rr * 8) * KD + d;
            *(__half2*)(g_proj_hi + o) = __halves2half2(h0, h1);
            *(__half2*)(g_proj_lo + o) = __halves2half2(l0, l1);
        }
    }
}

// ---------------- scores + softmax kernel ----------------
// CTA [64 t, 512 w] in 4 chunks of 128; grid (NT_/64, NB, 2).
__global__ __launch_bounds__(THREADS, 1) void scores_kernel() {
    extern __shared__ char sm[];
    const int t0 = blockIdx.x * 64, b = blockIdx.y, h = blockIdx.z;
    int tid = threadIdx.x, wid = tid >> 5, lane = tid & 31;
    int wr = wid >> 1, wcn = wid & 1;
    uint32_t sb = smem_u32(sm);
    const uint32_t oP = 0;                                   // 64 x 1040B
    const uint32_t oMh = 66560, oMl = 108544;                // 64 x 656B
    const uint32_t oPr[2][2] = {{150528, 168960}, {187392, 205824}};  // 128 x 144B
    float* mcS = (float*)(sm + 224256);                      // [64][8]
    float* scS = (float*)(sm + 226304);

    const __half* gmh = g_main_hi + ((size_t)b * NT_ + t0) * KD;
    const __half* gml = g_main_lo + ((size_t)b * NT_ + t0) * KD;
    const __half* gph = g_proj_hi + ((size_t)h * NB + b) * NW * KD;
    const __half* gpl = g_proj_lo + ((size_t)h * NB + b) * NW * KD;

    for (int i = tid; i < 64 * 40; i += THREADS) {
        int r = i / 40, c = i % 40;
        *(uint4*)(sm + oMh + r * 656 + c * 16) = *(const uint4*)(gmh + (size_t)r * KD + c * 8);
        *(uint4*)(sm + oMl + r * 656 + c * 16) = *(const uint4*)(gml + (size_t)r * KD + c * 8);
    }
    auto load_slice = [&](int buf, int s) {
        int wc = s / 5, ks = s % 5;
        const __half* sh = gph + (size_t)(wc * 128) * KD + ks * 64;
        const __half* sl = gpl + (size_t)(wc * 128) * KD + ks * 64;
        for (int i = tid; i < 128 * 8; i += THREADS) {
            int r = i >> 3, c = i & 7;
            cpa16(sb + oPr[buf][0] + r * 144 + c * 16, sh + (size_t)r * KD + c * 8);
            cpa16(sb + oPr[buf][1] + r * 144 + c * 16, sl + (size_t)r * KD + c * 8);
        }
        CP_COMMIT();
    };
    load_slice(0, 0);

    float acc[8][4];
    for (int s = 0; s < 20; s++) {
        int wc = s / 5, ks = s % 5;
        if (ks == 0) {
#pragma unroll
            for (int t = 0; t < 8; t++)
#pragma unroll
                for (int j = 0; j < 4; j++) acc[t][j] = 0.f;
        }
        CP_WAIT0();
        __syncthreads();
        if (s < 19) load_slice((s + 1) & 1, s + 1);
        int buf = s & 1;
#pragma unroll
        for (int k16 = 0; k16 < 4; k16++) {
            uint32_t aH[4], aL[4];
            int colA = ks * 64 + k16 * 16 + ((lane >> 4) << 3);
            uint32_t ar = sb + (wr * 16 + (lane & 15)) * 656 + colA * 2;
            ldm_x4(aH, oMh + ar);
            ldm_x4(aL, oMl + ar);
#pragma unroll
            for (int tp = 0; tp < 4; tp++) {
                int n = wcn * 64 + tp * 16;
                uint32_t r = n + (lane & 7) + ((lane >> 4) << 3);
                uint32_t c = k16 * 16 + (((lane >> 3) & 1) << 3);
                uint32_t bh[4], bl[4];
                ldm_x4(bh, sb + oPr[buf][0] + r * 144 + c * 2);
                ldm_x4(bl, sb + oPr[buf][1] + r * 144 + c * 2);
                mma16816(acc[2 * tp],     aH, bh[0], bh[1]);
                mma16816(acc[2 * tp + 1], aH, bh[2], bh[3]);
                mma16816(acc[2 * tp],     aH, bl[0], bl[1]);
                mma16816(acc[2 * tp + 1], aH, bl[2], bl[3]);
                mma16816(acc[2 * tp],     aL, bh[0], bh[1]);
                mma16816(acc[2 * tp + 1], aL, bh[2], bh[3]);
            }
        }
        if (ks == 4) {
            // chunk softmax (warp-local: this warp owns rows lr0/lr1, 64 of 128 chunk cols)
            int lr0 = wr * 16 + (lane >> 2), lr1 = lr0 + 8;
            float m0 = -1e30f, m1 = -1e30f;
#pragma unroll
            for (int t = 0; t < 8; t++) {
                m0 = fmaxf(m0, fmaxf(acc[t][0], acc[t][1]));
                m1 = fmaxf(m1, fmaxf(acc[t][2], acc[t][3]));
            }
            m0 = fmaxf(m0, __shfl_xor_sync(0xffffffffu, m0, 1));
            m0 = fmaxf(m0, __shfl_xor_sync(0xffffffffu, m0, 2));
            m1 = fmaxf(m1, __shfl_xor_sync(0xffffffffu, m1, 1));
            m1 = fmaxf(m1, __shfl_xor_sync(0xffffffffu, m1, 2));
            float s0 = 0.f, s1 = 0.f;
#pragma unroll
            for (int t = 0; t < 8; t++) {
                acc[t][0] = __expf(acc[t][0] - m0); s0 += acc[t][0];
                acc[t][1] = __expf(acc[t][1] - m0); s0 += acc[t][1];
                acc[t][2] = __expf(acc[t][2] - m1); s1 += acc[t][2];
                acc[t][3] = __expf(acc[t][3] - m1); s1 += acc[t][3];
            }
            s0 += __shfl_xor_sync(0xffffffffu, s0, 1);
            s0 += __shfl_xor_sync(0xffffffffu, s0, 2);
            s1 += __shfl_xor_sync(0xffffffffu, s1, 1);
            s1 += __shfl_xor_sync(0xffffffffu, s1, 2);
#pragma unroll
            for (int t = 0; t < 8; t++) {
                int cb = wc * 128 + wcn * 64 + t * 8 + 2 * (lane & 3);
                *(__half2*)(sm + oP + lr0 * 1040 + cb * 2) = __floats2half2_rn(acc[t][0], acc[t][1]);
                *(__half2*)(sm + oP + lr1 * 1040 + cb * 2) = __floats2half2_rn(acc[t][2], acc[t][3]);
            }
            if ((lane & 3) == 0) {
                int e = wc * 2 + wcn;
                mcS[lr0 * 8 + e] = m0; scS[lr0 * 8 + e] = s0;
                mcS[lr1 * 8 + e] = m1; scS[lr1 * 8 + e] = s1;
            }
        }
    }
    __syncthreads();
    // fixup: combine chunk stats, normalize, write P to gmem
    int row = tid >> 2, q = tid & 3;
    float mrow[8];
#pragma unroll
    for (int e = 0; e < 8; e++) mrow[e] = mcS[row * 8 + e];
    float M = mrow[0];
#pragma unroll
    for (int e = 1; e < 8; e++) M = fmaxf(M, mrow[e]);
    float l = 0.f;
#pragma unroll
    for (int e = 0; e < 8; e++) l += scS[row * 8 + e] * __expf(mrow[e] - M);
    float invl = 1.f / l;
    float f0 = __expf(mrow[q * 2] - M) * invl;
    float f1 = __expf(mrow[q * 2 + 1] - M) * invl;
    __half* gP = g_P + (((size_t)h * NB + b) * NT_ + t0 + row) * NW + q * 128;
#pragma unroll
    for (int j = 0; j < 16; j++) {
        float fac = (j < 8) ? f0 : f1;
        uint4 v = *(uint4*)(sm + oP + row * 1040 + (q * 128 + j * 8) * 2);
        __half2* hp = (__half2*)&v;
#pragma unroll
        for (int k = 0; k < 4; k++) {
            float2 f2 = __half22float2(hp[k]);
            hp[k] = __floats2half2_rn(f2.x * fac, f2.y * fac);
        }
        *(uint4*)(gP + j * 8) = v;
    }
}

// ---------------- out kernel: out = P @ attnT^T ----------------
// CTA [64 t, 320 d], grid (NT_/64, NB, 2). K=512 in 16 slices of 32.
__global__ __launch_bounds__(THREADS, 1) void out_kernel(float* __restrict__ out) {
    extern __shared__ char sm[];
    const int t0 = blockIdx.x * 64, b = blockIdx.y, h = blockIdx.z;
    int tid = threadIdx.x, wid = tid >> 5, lane = tid & 31;
    int wr = wid >> 1, wcn = wid & 1;
    uint32_t sb = smem_u32(sm);
    const uint32_t oP = 0;                                   // 64 x 1040B
    const uint32_t oB[2][2] = {{66560, 92160}, {117760, 143360}};  // 320 x 80B

    const __half* gP  = g_P + (((size_t)h * NB + b) * NT_ + t0) * NW;
    const __half* gth = g_attnT_hi + (size_t)b * KD * NW;
    const __half* gtl = g_attnT_lo + (size_t)b * KD * NW;

    for (int i = tid; i < 64 * 64; i += THREADS) {          // resident P
        int r = i >> 6, c = i & 63;
        *(uint4*)(sm + oP + r * 1040 + c * 16) = *(const uint4*)(gP + (size_t)r * NW + c * 8);
    }
    auto load_slice = [&](int buf, int ks) {
        for (int i = tid; i < 320 * 4; i += THREADS) {
            int r = i >> 2, c = i & 3;
            cpa16(sb + oB[buf][0] + r * 80 + c * 16, gth + (size_t)r * NW + ks * 32 + c * 8);
            cpa16(sb + oB[buf][1] + r * 80 + c * 16, gtl + (size_t)r * NW + ks * 32 + c * 8);
        }
        CP_COMMIT();
    };
    load_slice(0, 0);

    float acc[20][4];
#pragma unroll
    for (int t = 0; t < 20; t++)
#pragma unroll
        for (int j = 0; j < 4; j++) acc[t][j] = 0.f;

    for (int ks = 0; ks < 16; ks++) {
        CP_WAIT0();
        __syncthreads();
        if (ks < 15) load_slice((ks + 1) & 1, ks + 1);
        int buf = ks & 1;
#pragma unroll
        for (int k16 = 0; k16 < 2; k16++) {
            uint32_t a[4];
            ldm_x4(a, sb + oP + (wr * 16 + (lane & 15)) * 1040 +
                      (ks * 32 + k16 * 16 + ((lane >> 4) << 3)) * 2);
#pragma unroll
            for (int tp = 0; tp < 10; tp++) {
                int n = wcn * 160 + tp * 16;
                uint32_t r = n + (lane & 7) + ((lane >> 4) << 3);
                uint32_t c = k16 * 16 + (((lane >> 3) & 1) << 3);
                uint32_t bh[4], bl[4];
                ldm_x4(bh, sb + oB[buf][0] + r * 80 + c * 2);
                ldm_x4(bl, sb + oB[buf][1] + r * 80 + c * 2);
                mma16816(acc[2 * tp],     a, bh[0], bh[1]);
                mma16816(acc[2 * tp + 1], a, bh[2], bh[3]);
                mma16816(acc[2 * tp],     a, bl[0], bl[1]);
                mma16816(acc[2 * tp + 1], a, bl[2], bl[3]);
            }
        }
    }
    // epilogue
    size_t obase = ((size_t)h * NB + b) * NT_ + t0 + wr * 16 + (lane >> 2);
    float* p0 = out + obase * ND;
    float* p1 = out + (obase + 8) * ND;
#pragma unroll
    for (int t = 0; t < 20; t++) {
        int d = wcn * 160 + t * 8 + 2 * (lane & 3);
        if (d < ND)     { p0[d]     = acc[t][0]; p1[d]     = acc[t][2]; }
        if (d + 1 < ND) { p0[d + 1] = acc[t][1]; p1[d + 1] = acc[t][3]; }
    }
}

// ---------------------------------------------------------------------------
extern "C" void kernel_launch(void* const* d_in, const int* in_sizes, int n_in,
                              void* d_out, int out_size)
{
    const float* x1 = (const float*)d_in[0];  // [16,2048,300]
    const float* x2 = (const float*)d_in[1];  // [16,512,300]
    const float* W2 = (const float*)d_in[2];
    const float* W3 = (const float*)d_in[4];
    float* out = (float*)d_out;               // [2,16,2048,300]

    const int SC_SMEM = 228352, OUT_SMEM = 168960, PJ_SMEM = 186368;
    cudaFuncSetAttribute(scores_kernel, cudaFuncAttributeMaxDynamicSharedMemorySize, SC_SMEM);
    cudaFuncSetAttribute(out_kernel,    cudaFuncAttributeMaxDynamicSharedMemorySize, OUT_SMEM);
    cudaFuncSetAttribute(proj_kernel,   cudaFuncAttributeMaxDynamicSharedMemorySize, PJ_SMEM);

    prep_split<<<NB * NT_, KD>>>(x1, 0);
    prep_split<<<NB * NW, KD>>>(x2, 1);
    prep_W<<<dim3(KD, 2), KD>>>(W2, W3);
    prep_attnT<<<dim3(NW / 32, KD / 32, NB), dim3(32, 8)>>>(x2);

    proj_kernel<<<dim3(NW / 64, NB, 2), THREADS, PJ_SMEM>>>();
    scores_kernel<<<dim3(NT_ / 64, NB, 2), THREADS, SC_SMEM>>>();
    out_kernel<<<dim3(NT_ / 64, NB, 2), THREADS, OUT_SMEM>>>(out);
}